// round 5
// baseline (speedup 1.0000x reference)
#include <cuda_runtime.h>
#include <cuda_bf16.h>

// Problem constants (fixed by dataset): N = 131072 neurons, E = N*64 edges.
#define MAX_N 131072
#define NBLK  148          // <= SM count (148 B300 / 152 GB300): all co-resident
#define NTHR  1024

// Scratch (zero-initialized at load; phase C consumes AND re-zeros -> every
// graph replay starts from a clean state).
__device__ float g_dge[MAX_N];
__device__ float g_dgi[MAX_N];
// Packed spike code: 2 bits/neuron (0 silent, 1 exc spike, 2 inh spike). 32 KB.
__device__ unsigned int g_pack[MAX_N / 16];

// Software grid barrier state (generation counters grow monotonically across
// replays; behavior is replay-invariant).
__device__ unsigned int          g_bar_cnt[2];
__device__ volatile unsigned int g_bar_gen[2];

__device__ __forceinline__ void grid_barrier(int id) {
    __syncthreads();
    if (threadIdx.x == 0) {
        __threadfence();
        unsigned int gen = g_bar_gen[id];
        unsigned int ticket = atomicAdd(&g_bar_cnt[id], 1u);
        if (ticket == (unsigned int)(gridDim.x - 1)) {
            g_bar_cnt[id] = 0;
            __threadfence();
            g_bar_gen[id] = gen + 1u;
        } else {
            while (g_bar_gen[id] == gen) { }
        }
    }
    __syncthreads();
    __threadfence();
}

// ---------------------------------------------------------------------------
// Fused kernel: phase A (build packed codes) -> barrier -> phase B (edge
// scatter using smem-staged code table) -> barrier -> phase C (AdEx update).
// ---------------------------------------------------------------------------
__global__ void __launch_bounds__(NTHR, 1)
fused_kernel(
    const float* __restrict__ voltage, const float* __restrict__ adapt,
    const float* __restrict__ ge_in,   const float* __restrict__ gi_in,
    const float* __restrict__ stim,    const float* __restrict__ refr_in,
    const float* __restrict__ g_L,     const float* __restrict__ delta_T,
    const float* __restrict__ v_thresh,const float* __restrict__ v_rest,
    const float* __restrict__ Cm,      const float* __restrict__ aa,
    const float* __restrict__ bb,      const float* __restrict__ tau_w,
    const float* __restrict__ tau_ge,  const float* __restrict__ tau_gi,
    const float* __restrict__ E_ge,    const float* __restrict__ E_gi,
    const float* __restrict__ I_bias,  const float* __restrict__ stim_scale,
    const float* __restrict__ Qge,     const float* __restrict__ Qgi,
    const float* __restrict__ v_cut,   const float* __restrict__ v_reset,
    const float* __restrict__ t_refrac,
    const float* __restrict__ spiked,  const float* __restrict__ is_exc,
    const int*   __restrict__ src,     const int* __restrict__ dst,
    const float* __restrict__ dt_ptr,
    float* __restrict__ out,
    int n, int E)
{
    __shared__ unsigned int s_tab[MAX_N / 16];   // 32 KB code table

    const int tid  = threadIdx.x;
    const int gtid = blockIdx.x * NTHR + tid;
    const int nthreads = gridDim.x * NTHR;

    // ---------------- Phase A: build packed spike codes -------------------
    {
        int n4 = n >> 2;   // float4 groups (one byte of codes each)
        int i = gtid;
        unsigned int b = 0;
        if (i < n4) {
            float4 s = reinterpret_cast<const float4*>(spiked)[i];
            float4 x = reinterpret_cast<const float4*>(is_exc)[i];
            b |= (s.x != 0.0f ? (x.x != 0.0f ? 1u : 2u) : 0u) << 0;
            b |= (s.y != 0.0f ? (x.y != 0.0f ? 1u : 2u) : 0u) << 2;
            b |= (s.z != 0.0f ? (x.z != 0.0f ? 1u : 2u) : 0u) << 4;
            b |= (s.w != 0.0f ? (x.w != 0.0f ? 1u : 2u) : 0u) << 6;
        }
        unsigned int b1 = __shfl_down_sync(0xffffffffu, b, 1);
        unsigned int b2 = __shfl_down_sync(0xffffffffu, b, 2);
        unsigned int b3 = __shfl_down_sync(0xffffffffu, b, 3);
        if ((i & 3) == 0 && i < n4)
            g_pack[i >> 2] = b | (b1 << 8) | (b2 << 16) | (b3 << 24);
    }

    grid_barrier(0);

    // ---------------- Phase B: edge scatter -------------------------------
    {
        // stage code table: 8192 words / 1024 threads = 2 uint4 per thread
        const uint4* gp = reinterpret_cast<const uint4*>(g_pack);
        uint4* sp = reinterpret_cast<uint4*>(s_tab);
        sp[tid]        = gp[tid];
        sp[tid + NTHR] = gp[tid + NTHR];
        __syncthreads();

        const int G = E >> 2;   // int4 edge groups
        const int4* src4 = reinterpret_cast<const int4*>(src);
        const int4* dst4 = reinterpret_cast<const int4*>(dst);
#pragma unroll 2
        for (int g = gtid; g < G; g += nthreads) {
            int4 s = src4[g];
            int ss[4] = {s.x, s.y, s.z, s.w};
            unsigned int cc[4];
            unsigned int any = 0;
#pragma unroll
            for (int j = 0; j < 4; j++) {
                int idx = ss[j];
                cc[j] = (s_tab[idx >> 4] >> ((idx & 15) * 2)) & 3u;
                any |= cc[j];
            }
            if (any) {
                int4 d4 = dst4[g];
                int dd[4] = {d4.x, d4.y, d4.z, d4.w};
#pragma unroll
                for (int j = 0; j < 4; j++) {
                    unsigned int c = cc[j];
                    if (c) {
                        int d = dd[j];
                        if (c == 1u) atomicAdd(&g_dge[d], __ldg(Qge + d));
                        else         atomicAdd(&g_dgi[d], __ldg(Qgi + d));
                    }
                }
            }
        }
        // tail edges (E % 4), handled by thread 0 of block 0
        if (gtid == 0) {
            for (int e = G << 2; e < E; e++) {
                int idx = src[e];
                unsigned int c = (s_tab[idx >> 4] >> ((idx & 15) * 2)) & 3u;
                if (c) {
                    int d = dst[e];
                    if (c == 1u) atomicAdd(&g_dge[d], Qge[d]);
                    else         atomicAdd(&g_dgi[d], Qgi[d]);
                }
            }
        }
    }

    grid_barrier(1);

    // ---------------- Phase C: AdEx neuron update --------------------------
    for (int i = gtid; i < n; i += nthreads) {
        float dt = __ldg(dt_ptr);

        float v  = voltage[i];
        float w  = adapt[i];
        float ge = ge_in[i] + g_dge[i];
        float gi = gi_in[i] + g_dgi[i];
        g_dge[i] = 0.0f;
        g_dgi[i] = 0.0f;

        float gl = g_L[i];
        float dT = delta_T[i];
        float vr = v_rest[i];

        float I = I_bias[i] + stim_scale[i] * stim[i]
                + ge * (E_ge[i] - v) + gi * (E_gi[i] - v);
        float exp_term = gl * dT * expf(fminf((v - v_thresh[i]) / dT, 20.0f));
        float dv = (-gl * (v - vr) + exp_term - w + I) / Cm[i];
        float dw = (-w + aa[i] * (v - vr)) / tau_w[i];

        float refr = refr_in[i];
        float vn = (refr <= 0.0f) ? (v + dv * dt) : v;
        float wn = w + dw * dt;
        float geo = ge - (ge / tau_ge[i]) * dt;
        float gio = gi - (gi / tau_gi[i]) * dt;

        bool spk = vn > v_cut[i];
        float vout = spk ? v_reset[i] : vn;
        float wout = spk ? (wn + bb[i]) : wn;
        float rout = (spk ? t_refrac[i] : refr) - dt;

        out[0 * n + i] = vout;
        out[1 * n + i] = wout;
        out[2 * n + i] = geo;
        out[3 * n + i] = gio;
        out[4 * n + i] = rout;
        out[5 * n + i] = spk ? 1.0f : 0.0f;
    }
}

extern "C" void kernel_launch(void* const* d_in, const int* in_sizes, int n_in,
                              void* d_out, int out_size) {
    const float* voltage    = (const float*)d_in[0];
    const float* adapt      = (const float*)d_in[1];
    const float* ge         = (const float*)d_in[2];
    const float* gi         = (const float*)d_in[3];
    const float* stim       = (const float*)d_in[4];
    const float* refr       = (const float*)d_in[5];
    const float* g_L        = (const float*)d_in[6];
    const float* delta_T    = (const float*)d_in[7];
    const float* v_thresh   = (const float*)d_in[8];
    const float* v_rest     = (const float*)d_in[9];
    const float* C          = (const float*)d_in[10];
    const float* a          = (const float*)d_in[11];
    const float* b          = (const float*)d_in[12];
    const float* tau_w      = (const float*)d_in[13];
    const float* tau_ge     = (const float*)d_in[14];
    const float* tau_gi     = (const float*)d_in[15];
    const float* E_ge       = (const float*)d_in[16];
    const float* E_gi       = (const float*)d_in[17];
    const float* I_bias     = (const float*)d_in[18];
    const float* stim_scale = (const float*)d_in[19];
    const float* Q_ge       = (const float*)d_in[20];
    const float* Q_gi       = (const float*)d_in[21];
    const float* v_cut      = (const float*)d_in[22];
    const float* v_reset    = (const float*)d_in[23];
    const float* t_refrac   = (const float*)d_in[24];
    const float* spiked     = (const float*)d_in[25];
    const float* is_exc     = (const float*)d_in[26];
    const int*   edge_index = (const int*)d_in[27];
    const float* dt         = (const float*)d_in[28];

    int n = in_sizes[0];
    int E = in_sizes[27] / 2;
    const int* src = edge_index;
    const int* dst = edge_index + E;

    fused_kernel<<<NBLK, NTHR>>>(
        voltage, adapt, ge, gi, stim, refr,
        g_L, delta_T, v_thresh, v_rest, C, a, b, tau_w, tau_ge, tau_gi,
        E_ge, E_gi, I_bias, stim_scale, Q_ge, Q_gi,
        v_cut, v_reset, t_refrac, spiked, is_exc,
        src, dst, dt, (float*)d_out, n, E);
}

// round 6
// speedup vs baseline: 1.6038x; 1.6038x over previous
#include <cuda_runtime.h>
#include <cuda_bf16.h>

// Problem constants (fixed by dataset): N = 131072 neurons, E = N*64 edges.
#define MAX_N 131072
#define NWORDS (MAX_N / 32)     // 4096 words = 16 KB per bitmask

// Scratch: zero-initialized at load; neuron kernel consumes AND re-zeros the
// deltas so every graph replay starts clean (deterministic).
__device__ float g_dge[MAX_N];
__device__ float g_dgi[MAX_N];
// Bit-planar spike tables: 1 bit/neuron.
__device__ unsigned int g_act[NWORDS];   // neuron spiked last step
__device__ unsigned int g_exc[NWORDS];   // spiked AND excitatory

// ---------------------------------------------------------------------------
// Kernel 1: build bitmasks. 1 neuron/thread, warp ballots, lane 0 writes.
// Bool inputs arrive as float32 (0.0 / 1.0).
// ---------------------------------------------------------------------------
__global__ void build_mask_kernel(const float* __restrict__ spiked,
                                  const float* __restrict__ is_exc,
                                  int n) {
    int i = blockIdx.x * blockDim.x + threadIdx.x;
    if (i >= n) return;
    bool s = spiked[i] != 0.0f;
    bool x = is_exc[i] != 0.0f;
    unsigned int act = __ballot_sync(0xffffffffu, s);
    unsigned int exc = __ballot_sync(0xffffffffu, s && x);
    if ((i & 31) == 0) {
        g_act[i >> 5] = act;
        g_exc[i >> 5] = exc;
    }
}

// ---------------------------------------------------------------------------
// Kernel 2: event-driven synaptic scatter.
// 16 KB act bitmask + 16 KB exc bitmask staged in smem. Each thread handles
// 16 edges via 4 front-batched int4 src loads (high MLP). dst int4 loaded only
// for groups with >=1 active source (~18.5%); exc lookup + atomic only for the
// ~5% active edges.
// ---------------------------------------------------------------------------
#define EDGE_BLOCK 1024
#define EDGE_GPT   4                              // int4 groups per thread
#define EDGE_PER_BLOCK (EDGE_BLOCK * EDGE_GPT * 4)  // 16384 edges

__global__ void __launch_bounds__(EDGE_BLOCK, 2)
edge_kernel(const int* __restrict__ src,
            const int* __restrict__ dst,
            const float* __restrict__ Qge,
            const float* __restrict__ Qgi,
            int E) {
    __shared__ unsigned int s_act[NWORDS];   // 16 KB
    __shared__ unsigned int s_exc[NWORDS];   // 16 KB

    const int tid = threadIdx.x;
    // stage tables: 4096 words each -> 1 uint4 per thread per table
    {
        const uint4* ga = reinterpret_cast<const uint4*>(g_act);
        const uint4* gx = reinterpret_cast<const uint4*>(g_exc);
        reinterpret_cast<uint4*>(s_act)[tid] = ga[tid];
        reinterpret_cast<uint4*>(s_exc)[tid] = gx[tid];
    }
    __syncthreads();

    long base = (long)blockIdx.x * EDGE_PER_BLOCK;
    if (base + EDGE_PER_BLOCK <= E) {
        const int4* src4 = reinterpret_cast<const int4*>(src + base);
        const int4* dst4 = reinterpret_cast<const int4*>(dst + base);
        // front-batch 4 int4 src loads (16 edges) for MLP
        int4 sb[EDGE_GPT];
#pragma unroll
        for (int k = 0; k < EDGE_GPT; k++)
            sb[k] = src4[tid + k * EDGE_BLOCK];
#pragma unroll
        for (int k = 0; k < EDGE_GPT; k++) {
            int ss[4] = {sb[k].x, sb[k].y, sb[k].z, sb[k].w};
            unsigned int aa[4];
            unsigned int any = 0;
#pragma unroll
            for (int j = 0; j < 4; j++) {
                aa[j] = (s_act[ss[j] >> 5] >> (ss[j] & 31)) & 1u;
                any |= aa[j];
            }
            if (any) {
                int4 d4 = dst4[tid + k * EDGE_BLOCK];
                int dd[4] = {d4.x, d4.y, d4.z, d4.w};
#pragma unroll
                for (int j = 0; j < 4; j++) {
                    if (aa[j]) {
                        int idx = ss[j];
                        int d = dd[j];
                        bool e = (s_exc[idx >> 5] >> (idx & 31)) & 1u;
                        if (e) atomicAdd(&g_dge[d], __ldg(Qge + d));
                        else   atomicAdd(&g_dgi[d], __ldg(Qgi + d));
                    }
                }
            }
        }
    } else {
        for (long e = base + tid; e < E; e += EDGE_BLOCK) {
            int idx = src[e];
            if ((s_act[idx >> 5] >> (idx & 31)) & 1u) {
                int d = dst[e];
                bool ex = (s_exc[idx >> 5] >> (idx & 31)) & 1u;
                if (ex) atomicAdd(&g_dge[d], Qge[d]);
                else    atomicAdd(&g_dgi[d], Qgi[d]);
            }
        }
    }
}

// ---------------------------------------------------------------------------
// Kernel 3: AdEx neuron update, float4-vectorized (4 neurons/thread).
// Writes the 6 outputs and re-zeros the delta scratch for the next replay.
// ---------------------------------------------------------------------------
__global__ void neuron_kernel(
    const float4* __restrict__ voltage, const float4* __restrict__ adapt,
    const float4* __restrict__ ge_in,   const float4* __restrict__ gi_in,
    const float4* __restrict__ stim,    const float4* __restrict__ refr_in,
    const float4* __restrict__ g_L,     const float4* __restrict__ delta_T,
    const float4* __restrict__ v_thresh,const float4* __restrict__ v_rest,
    const float4* __restrict__ Cm,      const float4* __restrict__ aa,
    const float4* __restrict__ bb,      const float4* __restrict__ tau_w,
    const float4* __restrict__ tau_ge,  const float4* __restrict__ tau_gi,
    const float4* __restrict__ E_ge,    const float4* __restrict__ E_gi,
    const float4* __restrict__ I_bias,  const float4* __restrict__ stim_scale,
    const float4* __restrict__ v_cut,   const float4* __restrict__ v_reset,
    const float4* __restrict__ t_refrac,
    const float* __restrict__ dt_ptr,
    float* __restrict__ out, int n4) {
    int i = blockIdx.x * blockDim.x + threadIdx.x;
    if (i >= n4) return;
    int n = n4 * 4;

    float dt = __ldg(dt_ptr);

    float4 v4  = voltage[i];
    float4 w4  = adapt[i];
    float4 ge4 = ge_in[i];
    float4 gi4 = gi_in[i];
    float4 dge4 = *reinterpret_cast<const float4*>(g_dge + i * 4);
    float4 dgi4 = *reinterpret_cast<const float4*>(g_dgi + i * 4);
    *reinterpret_cast<float4*>(g_dge + i * 4) = make_float4(0.f, 0.f, 0.f, 0.f);
    *reinterpret_cast<float4*>(g_dgi + i * 4) = make_float4(0.f, 0.f, 0.f, 0.f);

    float4 gl4 = g_L[i];
    float4 dT4 = delta_T[i];
    float4 vt4 = v_thresh[i];
    float4 vr4 = v_rest[i];
    float4 C4  = Cm[i];
    float4 a4  = aa[i];
    float4 b4  = bb[i];
    float4 tw4 = tau_w[i];
    float4 tge4 = tau_ge[i];
    float4 tgi4 = tau_gi[i];
    float4 Ege4 = E_ge[i];
    float4 Egi4 = E_gi[i];
    float4 Ib4  = I_bias[i];
    float4 ssc4 = stim_scale[i];
    float4 st4  = stim[i];
    float4 vc4  = v_cut[i];
    float4 vrs4 = v_reset[i];
    float4 tr4  = t_refrac[i];
    float4 rf4  = refr_in[i];

    float4 vo, wo, geo, gio, ro, so;

#define LANE(F)                                                                 \
    {                                                                           \
        float v = v4.F, w = w4.F;                                               \
        float ge = ge4.F + dge4.F;                                              \
        float gi = gi4.F + dgi4.F;                                              \
        float gl = gl4.F, dT = dT4.F, vr = vr4.F;                               \
        float I = Ib4.F + ssc4.F * st4.F + ge * (Ege4.F - v) + gi * (Egi4.F - v); \
        float exp_term = gl * dT * expf(fminf((v - vt4.F) / dT, 20.0f));        \
        float dv = (-gl * (v - vr) + exp_term - w + I) / C4.F;                  \
        float dw = (-w + a4.F * (v - vr)) / tw4.F;                              \
        float refr = rf4.F;                                                     \
        float vn = (refr <= 0.0f) ? (v + dv * dt) : v;                          \
        float wn = w + dw * dt;                                                 \
        geo.F = ge - (ge / tge4.F) * dt;                                        \
        gio.F = gi - (gi / tgi4.F) * dt;                                        \
        bool spk = vn > vc4.F;                                                  \
        vo.F = spk ? vrs4.F : vn;                                               \
        wo.F = spk ? (wn + b4.F) : wn;                                          \
        ro.F = (spk ? tr4.F : refr) - dt;                                       \
        so.F = spk ? 1.0f : 0.0f;                                               \
    }
    LANE(x) LANE(y) LANE(z) LANE(w)
#undef LANE

    *reinterpret_cast<float4*>(out + 0 * n + i * 4) = vo;
    *reinterpret_cast<float4*>(out + 1 * n + i * 4) = wo;
    *reinterpret_cast<float4*>(out + 2 * n + i * 4) = geo;
    *reinterpret_cast<float4*>(out + 3 * n + i * 4) = gio;
    *reinterpret_cast<float4*>(out + 4 * n + i * 4) = ro;
    *reinterpret_cast<float4*>(out + 5 * n + i * 4) = so;
}

extern "C" void kernel_launch(void* const* d_in, const int* in_sizes, int n_in,
                              void* d_out, int out_size) {
    const float* voltage    = (const float*)d_in[0];
    const float* adapt      = (const float*)d_in[1];
    const float* ge         = (const float*)d_in[2];
    const float* gi         = (const float*)d_in[3];
    const float* stim       = (const float*)d_in[4];
    const float* refr       = (const float*)d_in[5];
    const float* g_L        = (const float*)d_in[6];
    const float* delta_T    = (const float*)d_in[7];
    const float* v_thresh   = (const float*)d_in[8];
    const float* v_rest     = (const float*)d_in[9];
    const float* C          = (const float*)d_in[10];
    const float* a          = (const float*)d_in[11];
    const float* b          = (const float*)d_in[12];
    const float* tau_w      = (const float*)d_in[13];
    const float* tau_ge     = (const float*)d_in[14];
    const float* tau_gi     = (const float*)d_in[15];
    const float* E_ge       = (const float*)d_in[16];
    const float* E_gi       = (const float*)d_in[17];
    const float* I_bias     = (const float*)d_in[18];
    const float* stim_scale = (const float*)d_in[19];
    const float* Q_ge       = (const float*)d_in[20];
    const float* Q_gi       = (const float*)d_in[21];
    const float* v_cut      = (const float*)d_in[22];
    const float* v_reset    = (const float*)d_in[23];
    const float* t_refrac   = (const float*)d_in[24];
    const float* spiked     = (const float*)d_in[25];
    const float* is_exc     = (const float*)d_in[26];
    const int*   edge_index = (const int*)d_in[27];
    const float* dt         = (const float*)d_in[28];

    int n = in_sizes[0];
    int n4 = n / 4;
    int E = in_sizes[27] / 2;
    const int* src = edge_index;
    const int* dst = edge_index + E;

    build_mask_kernel<<<(n + 255) / 256, 256>>>(spiked, is_exc, n);

    int edge_blocks = (E + EDGE_PER_BLOCK - 1) / EDGE_PER_BLOCK;
    edge_kernel<<<edge_blocks, EDGE_BLOCK>>>(src, dst, Q_ge, Q_gi, E);

    neuron_kernel<<<(n4 + 63) / 64, 64>>>(
        (const float4*)voltage, (const float4*)adapt,
        (const float4*)ge, (const float4*)gi,
        (const float4*)stim, (const float4*)refr,
        (const float4*)g_L, (const float4*)delta_T,
        (const float4*)v_thresh, (const float4*)v_rest,
        (const float4*)C, (const float4*)a, (const float4*)b,
        (const float4*)tau_w, (const float4*)tau_ge, (const float4*)tau_gi,
        (const float4*)E_ge, (const float4*)E_gi,
        (const float4*)I_bias, (const float4*)stim_scale,
        (const float4*)v_cut, (const float4*)v_reset, (const float4*)t_refrac,
        dt, (float*)d_out, n4);
}

// round 7
// speedup vs baseline: 1.7369x; 1.0830x over previous
#include <cuda_runtime.h>
#include <cuda_bf16.h>

// Problem constants (fixed by dataset): N = 131072 neurons, E = N*64 edges.
#define MAX_N 131072
#define NWORDS (MAX_N / 32)     // 4096 words = 16 KB per bitmask

// Scratch: zero-initialized at load; neuron kernel consumes AND re-zeros the
// deltas so every graph replay starts clean (deterministic).
__device__ float g_dge[MAX_N];
__device__ float g_dgi[MAX_N];
// Bit-planar spike tables: 1 bit/neuron.
__device__ unsigned int g_act[NWORDS];   // neuron spiked last step
__device__ unsigned int g_exc[NWORDS];   // spiked AND excitatory

// ---------------------------------------------------------------------------
// Kernel 1: build bitmasks. 1 neuron/thread, warp ballots, lane 0 writes.
// Bool inputs arrive as float32 (0.0 / 1.0).
// ---------------------------------------------------------------------------
__global__ void build_mask_kernel(const float* __restrict__ spiked,
                                  const float* __restrict__ is_exc,
                                  int n) {
    int i = blockIdx.x * blockDim.x + threadIdx.x;
    if (i >= n) return;
    bool s = spiked[i] != 0.0f;
    bool x = is_exc[i] != 0.0f;
    unsigned int act = __ballot_sync(0xffffffffu, s);
    unsigned int exc = __ballot_sync(0xffffffffu, s && x);
    if ((i & 31) == 0) {
        g_act[i >> 5] = act;
        g_exc[i >> 5] = exc;
    }
}

// ---------------------------------------------------------------------------
// Kernel 2: event-driven synaptic scatter (PDL secondary of build_mask).
// Front-batches src int4 loads BEFORE cudaGridDependencySynchronize so the
// build kernel hides under the DRAM ramp. 16 KB act + 16 KB exc bitmasks
// staged in smem; dst int4 loaded only for groups with an active source.
// ---------------------------------------------------------------------------
#define EDGE_BLOCK 1024
#define EDGE_GPT   4                              // int4 groups per thread
#define EDGE_PER_BLOCK (EDGE_BLOCK * EDGE_GPT * 4)  // 16384 edges

__global__ void __launch_bounds__(EDGE_BLOCK, 2)
edge_kernel(const int* __restrict__ src,
            const int* __restrict__ dst,
            const float* __restrict__ Qge,
            const float* __restrict__ Qgi,
            int E) {
    __shared__ unsigned int s_act[NWORDS];   // 16 KB
    __shared__ unsigned int s_exc[NWORDS];   // 16 KB

    const int tid = threadIdx.x;
    long base = (long)blockIdx.x * EDGE_PER_BLOCK;
    bool full = (base + EDGE_PER_BLOCK) <= (long)E;

    // ---- pre-dependency work: start streaming src (independent of build) ----
    int4 sb[EDGE_GPT];
    if (full) {
        const int4* src4 = reinterpret_cast<const int4*>(src + base);
#pragma unroll
        for (int k = 0; k < EDGE_GPT; k++)
            sb[k] = src4[tid + k * EDGE_BLOCK];
    }

    // ---- wait for build_mask results, then stage tables ----
    cudaGridDependencySynchronize();
    {
        const uint4* ga = reinterpret_cast<const uint4*>(g_act);
        const uint4* gx = reinterpret_cast<const uint4*>(g_exc);
        reinterpret_cast<uint4*>(s_act)[tid] = ga[tid];
        reinterpret_cast<uint4*>(s_exc)[tid] = gx[tid];
    }
    __syncthreads();

    if (full) {
        const int4* dst4 = reinterpret_cast<const int4*>(dst + base);
#pragma unroll
        for (int k = 0; k < EDGE_GPT; k++) {
            int ss[4] = {sb[k].x, sb[k].y, sb[k].z, sb[k].w};
            unsigned int aa[4];
            unsigned int any = 0;
#pragma unroll
            for (int j = 0; j < 4; j++) {
                aa[j] = (s_act[ss[j] >> 5] >> (ss[j] & 31)) & 1u;
                any |= aa[j];
            }
            if (any) {
                int4 d4 = dst4[tid + k * EDGE_BLOCK];
                int dd[4] = {d4.x, d4.y, d4.z, d4.w};
#pragma unroll
                for (int j = 0; j < 4; j++) {
                    if (aa[j]) {
                        int idx = ss[j];
                        int d = dd[j];
                        bool e = (s_exc[idx >> 5] >> (idx & 31)) & 1u;
                        if (e) atomicAdd(&g_dge[d], __ldg(Qge + d));
                        else   atomicAdd(&g_dgi[d], __ldg(Qgi + d));
                    }
                }
            }
        }
    } else {
        for (long e = base + tid; e < E; e += EDGE_BLOCK) {
            int idx = src[e];
            if ((s_act[idx >> 5] >> (idx & 31)) & 1u) {
                int d = dst[e];
                bool ex = (s_exc[idx >> 5] >> (idx & 31)) & 1u;
                if (ex) atomicAdd(&g_dge[d], Qge[d]);
                else    atomicAdd(&g_dgi[d], Qgi[d]);
            }
        }
    }
}

// ---------------------------------------------------------------------------
// Kernel 3: AdEx neuron update, float4-vectorized (PDL secondary of edge).
// All parameter streams are loaded BEFORE the dependency sync; only the
// dge/dgi consumption waits for the edge atomics.
// ---------------------------------------------------------------------------
__global__ void neuron_kernel(
    const float4* __restrict__ voltage, const float4* __restrict__ adapt,
    const float4* __restrict__ ge_in,   const float4* __restrict__ gi_in,
    const float4* __restrict__ stim,    const float4* __restrict__ refr_in,
    const float4* __restrict__ g_L,     const float4* __restrict__ delta_T,
    const float4* __restrict__ v_thresh,const float4* __restrict__ v_rest,
    const float4* __restrict__ Cm,      const float4* __restrict__ aa,
    const float4* __restrict__ bb,      const float4* __restrict__ tau_w,
    const float4* __restrict__ tau_ge,  const float4* __restrict__ tau_gi,
    const float4* __restrict__ E_ge,    const float4* __restrict__ E_gi,
    const float4* __restrict__ I_bias,  const float4* __restrict__ stim_scale,
    const float4* __restrict__ v_cut,   const float4* __restrict__ v_reset,
    const float4* __restrict__ t_refrac,
    const float* __restrict__ dt_ptr,
    float* __restrict__ out, int n4) {
    int i = blockIdx.x * blockDim.x + threadIdx.x;
    if (i >= n4) { cudaGridDependencySynchronize(); return; }
    int n = n4 * 4;

    // ---- pre-dependency loads (independent of edge kernel output) ----
    float dt = __ldg(dt_ptr);
    float4 v4  = voltage[i];
    float4 w4  = adapt[i];
    float4 ge4 = ge_in[i];
    float4 gi4 = gi_in[i];
    float4 gl4 = g_L[i];
    float4 dT4 = delta_T[i];
    float4 vt4 = v_thresh[i];
    float4 vr4 = v_rest[i];
    float4 C4  = Cm[i];
    float4 a4  = aa[i];
    float4 b4  = bb[i];
    float4 tw4 = tau_w[i];
    float4 tge4 = tau_ge[i];
    float4 tgi4 = tau_gi[i];
    float4 Ege4 = E_ge[i];
    float4 Egi4 = E_gi[i];
    float4 Ib4  = I_bias[i];
    float4 ssc4 = stim_scale[i];
    float4 st4  = stim[i];
    float4 vc4  = v_cut[i];
    float4 vrs4 = v_reset[i];
    float4 tr4  = t_refrac[i];
    float4 rf4  = refr_in[i];

    // ---- wait for edge atomics, then consume + re-zero deltas ----
    cudaGridDependencySynchronize();
    float4 dge4 = *reinterpret_cast<const float4*>(g_dge + i * 4);
    float4 dgi4 = *reinterpret_cast<const float4*>(g_dgi + i * 4);
    *reinterpret_cast<float4*>(g_dge + i * 4) = make_float4(0.f, 0.f, 0.f, 0.f);
    *reinterpret_cast<float4*>(g_dgi + i * 4) = make_float4(0.f, 0.f, 0.f, 0.f);

    float4 vo, wo, geo, gio, ro, so;

#define LANE(F)                                                                 \
    {                                                                           \
        float v = v4.F, w = w4.F;                                               \
        float ge = ge4.F + dge4.F;                                              \
        float gi = gi4.F + dgi4.F;                                              \
        float gl = gl4.F, dT = dT4.F, vr = vr4.F;                               \
        float I = Ib4.F + ssc4.F * st4.F + ge * (Ege4.F - v) + gi * (Egi4.F - v); \
        float exp_term = gl * dT * expf(fminf((v - vt4.F) / dT, 20.0f));        \
        float dv = (-gl * (v - vr) + exp_term - w + I) / C4.F;                  \
        float dw = (-w + a4.F * (v - vr)) / tw4.F;                              \
        float refr = rf4.F;                                                     \
        float vn = (refr <= 0.0f) ? (v + dv * dt) : v;                          \
        float wn = w + dw * dt;                                                 \
        geo.F = ge - (ge / tge4.F) * dt;                                        \
        gio.F = gi - (gi / tgi4.F) * dt;                                        \
        bool spk = vn > vc4.F;                                                  \
        vo.F = spk ? vrs4.F : vn;                                               \
        wo.F = spk ? (wn + b4.F) : wn;                                          \
        ro.F = (spk ? tr4.F : refr) - dt;                                       \
        so.F = spk ? 1.0f : 0.0f;                                               \
    }
    LANE(x) LANE(y) LANE(z) LANE(w)
#undef LANE

    *reinterpret_cast<float4*>(out + 0 * n + i * 4) = vo;
    *reinterpret_cast<float4*>(out + 1 * n + i * 4) = wo;
    *reinterpret_cast<float4*>(out + 2 * n + i * 4) = geo;
    *reinterpret_cast<float4*>(out + 3 * n + i * 4) = gio;
    *reinterpret_cast<float4*>(out + 4 * n + i * 4) = ro;
    *reinterpret_cast<float4*>(out + 5 * n + i * 4) = so;
}

extern "C" void kernel_launch(void* const* d_in, const int* in_sizes, int n_in,
                              void* d_out, int out_size) {
    const float* voltage    = (const float*)d_in[0];
    const float* adapt      = (const float*)d_in[1];
    const float* ge         = (const float*)d_in[2];
    const float* gi         = (const float*)d_in[3];
    const float* stim       = (const float*)d_in[4];
    const float* refr       = (const float*)d_in[5];
    const float* g_L        = (const float*)d_in[6];
    const float* delta_T    = (const float*)d_in[7];
    const float* v_thresh   = (const float*)d_in[8];
    const float* v_rest     = (const float*)d_in[9];
    const float* C          = (const float*)d_in[10];
    const float* a          = (const float*)d_in[11];
    const float* b          = (const float*)d_in[12];
    const float* tau_w      = (const float*)d_in[13];
    const float* tau_ge     = (const float*)d_in[14];
    const float* tau_gi     = (const float*)d_in[15];
    const float* E_ge       = (const float*)d_in[16];
    const float* E_gi       = (const float*)d_in[17];
    const float* I_bias     = (const float*)d_in[18];
    const float* stim_scale = (const float*)d_in[19];
    const float* Q_ge       = (const float*)d_in[20];
    const float* Q_gi       = (const float*)d_in[21];
    const float* v_cut      = (const float*)d_in[22];
    const float* v_reset    = (const float*)d_in[23];
    const float* t_refrac   = (const float*)d_in[24];
    const float* spiked     = (const float*)d_in[25];
    const float* is_exc     = (const float*)d_in[26];
    const int*   edge_index = (const int*)d_in[27];
    const float* dt         = (const float*)d_in[28];

    int n = in_sizes[0];
    int n4 = n / 4;
    int E = in_sizes[27] / 2;
    const int* src = edge_index;
    const int* dst = edge_index + E;

    build_mask_kernel<<<(n + 255) / 256, 256>>>(spiked, is_exc, n);

    // PDL attribute: secondary may launch before primary completes; ordering
    // is enforced by cudaGridDependencySynchronize() inside the kernels.
    cudaLaunchAttribute pdl[1];
    pdl[0].id = cudaLaunchAttributeProgrammaticStreamSerialization;
    pdl[0].val.programmaticStreamSerializationAllowed = 1;

    {
        cudaLaunchConfig_t cfg = {};
        int edge_blocks = (E + EDGE_PER_BLOCK - 1) / EDGE_PER_BLOCK;
        cfg.gridDim  = dim3(edge_blocks, 1, 1);
        cfg.blockDim = dim3(EDGE_BLOCK, 1, 1);
        cfg.attrs = pdl;
        cfg.numAttrs = 1;
        cudaLaunchKernelEx(&cfg, edge_kernel, src, dst, Q_ge, Q_gi, E);
    }

    {
        cudaLaunchConfig_t cfg = {};
        cfg.gridDim  = dim3((n4 + 63) / 64, 1, 1);
        cfg.blockDim = dim3(64, 1, 1);
        cfg.attrs = pdl;
        cfg.numAttrs = 1;
        cudaLaunchKernelEx(&cfg, neuron_kernel,
            (const float4*)voltage, (const float4*)adapt,
            (const float4*)ge, (const float4*)gi,
            (const float4*)stim, (const float4*)refr,
            (const float4*)g_L, (const float4*)delta_T,
            (const float4*)v_thresh, (const float4*)v_rest,
            (const float4*)C, (const float4*)a, (const float4*)b,
            (const float4*)tau_w, (const float4*)tau_ge, (const float4*)tau_gi,
            (const float4*)E_ge, (const float4*)E_gi,
            (const float4*)I_bias, (const float4*)stim_scale,
            (const float4*)v_cut, (const float4*)v_reset, (const float4*)t_refrac,
            dt, (float*)d_out, n4);
    }
}

// round 8
// speedup vs baseline: 2.0732x; 1.1936x over previous
#include <cuda_runtime.h>
#include <cuda_bf16.h>

// Problem constants (fixed by dataset): N = 131072 neurons, E = N*64 edges.
#define MAX_N 131072
#define NWORDS (MAX_N / 32)     // 4096 words = 16 KB per bitmask

// Scratch: zero-initialized at load; neuron kernel consumes AND re-zeros so
// every graph replay starts clean (deterministic).
// Packed event counts: low 16 bits = excitatory arrivals, high 16 = inhibitory.
__device__ unsigned int g_cnt[MAX_N];
// Bit-planar spike tables: 1 bit/neuron.
__device__ unsigned int g_act[NWORDS];   // neuron spiked last step
__device__ unsigned int g_exc[NWORDS];   // spiked AND excitatory

// ---------------------------------------------------------------------------
// Kernel 1: build bitmasks. 1 neuron/thread, warp ballots, lane 0 writes.
// Bool inputs arrive as float32 (0.0 / 1.0).
// ---------------------------------------------------------------------------
__global__ void build_mask_kernel(const float* __restrict__ spiked,
                                  const float* __restrict__ is_exc,
                                  int n) {
    int i = blockIdx.x * blockDim.x + threadIdx.x;
    if (i >= n) return;
    bool s = spiked[i] != 0.0f;
    bool x = is_exc[i] != 0.0f;
    unsigned int act = __ballot_sync(0xffffffffu, s);
    unsigned int exc = __ballot_sync(0xffffffffu, s && x);
    if ((i & 31) == 0) {
        g_act[i >> 5] = act;
        g_exc[i >> 5] = exc;
    }
}

// ---------------------------------------------------------------------------
// Kernel 2: event-driven synaptic scatter (PDL secondary of build_mask).
// Front-batches src int4 loads BEFORE cudaGridDependencySynchronize so the
// build kernel hides under the DRAM ramp. 16 KB act + 16 KB exc bitmasks
// staged in smem; dst int4 loaded only for groups with an active source.
// Inner op per active edge: ONE packed-int atomic (no value gather).
// ---------------------------------------------------------------------------
#define EDGE_BLOCK 1024
#define EDGE_GPT   4                              // int4 groups per thread
#define EDGE_PER_BLOCK (EDGE_BLOCK * EDGE_GPT * 4)  // 16384 edges

__global__ void __launch_bounds__(EDGE_BLOCK, 2)
edge_kernel(const int* __restrict__ src,
            const int* __restrict__ dst,
            int E) {
    __shared__ unsigned int s_act[NWORDS];   // 16 KB
    __shared__ unsigned int s_exc[NWORDS];   // 16 KB

    const int tid = threadIdx.x;
    long base = (long)blockIdx.x * EDGE_PER_BLOCK;
    bool full = (base + EDGE_PER_BLOCK) <= (long)E;

    // ---- pre-dependency work: start streaming src (independent of build) ----
    int4 sb[EDGE_GPT];
    if (full) {
        const int4* src4 = reinterpret_cast<const int4*>(src + base);
#pragma unroll
        for (int k = 0; k < EDGE_GPT; k++)
            sb[k] = src4[tid + k * EDGE_BLOCK];
    }

    // ---- wait for build_mask results, then stage tables ----
    cudaGridDependencySynchronize();
    {
        const uint4* ga = reinterpret_cast<const uint4*>(g_act);
        const uint4* gx = reinterpret_cast<const uint4*>(g_exc);
        reinterpret_cast<uint4*>(s_act)[tid] = ga[tid];
        reinterpret_cast<uint4*>(s_exc)[tid] = gx[tid];
    }
    __syncthreads();

    if (full) {
        const int4* dst4 = reinterpret_cast<const int4*>(dst + base);
#pragma unroll
        for (int k = 0; k < EDGE_GPT; k++) {
            int ss[4] = {sb[k].x, sb[k].y, sb[k].z, sb[k].w};
            unsigned int aa[4];
            unsigned int any = 0;
#pragma unroll
            for (int j = 0; j < 4; j++) {
                aa[j] = (s_act[ss[j] >> 5] >> (ss[j] & 31)) & 1u;
                any |= aa[j];
            }
            if (any) {
                int4 d4 = dst4[tid + k * EDGE_BLOCK];
                int dd[4] = {d4.x, d4.y, d4.z, d4.w};
#pragma unroll
                for (int j = 0; j < 4; j++) {
                    if (aa[j]) {
                        int idx = ss[j];
                        bool e = (s_exc[idx >> 5] >> (idx & 31)) & 1u;
                        atomicAdd(&g_cnt[dd[j]], e ? 1u : 65536u);
                    }
                }
            }
        }
    } else {
        for (long e = base + tid; e < E; e += EDGE_BLOCK) {
            int idx = src[e];
            if ((s_act[idx >> 5] >> (idx & 31)) & 1u) {
                bool ex = (s_exc[idx >> 5] >> (idx & 31)) & 1u;
                atomicAdd(&g_cnt[dst[e]], ex ? 1u : 65536u);
            }
        }
    }
}

// ---------------------------------------------------------------------------
// Kernel 3: AdEx neuron update, float4-vectorized (PDL secondary of edge).
// All parameter streams are loaded BEFORE the dependency sync; only the
// packed-count consumption waits for the edge atomics.
// ge += Q_ge * exc_count ; gi += Q_gi * inh_count  (Q read coalesced here).
// ---------------------------------------------------------------------------
__global__ void neuron_kernel(
    const float4* __restrict__ voltage, const float4* __restrict__ adapt,
    const float4* __restrict__ ge_in,   const float4* __restrict__ gi_in,
    const float4* __restrict__ stim,    const float4* __restrict__ refr_in,
    const float4* __restrict__ g_L,     const float4* __restrict__ delta_T,
    const float4* __restrict__ v_thresh,const float4* __restrict__ v_rest,
    const float4* __restrict__ Cm,      const float4* __restrict__ aa,
    const float4* __restrict__ bb,      const float4* __restrict__ tau_w,
    const float4* __restrict__ tau_ge,  const float4* __restrict__ tau_gi,
    const float4* __restrict__ E_ge,    const float4* __restrict__ E_gi,
    const float4* __restrict__ I_bias,  const float4* __restrict__ stim_scale,
    const float4* __restrict__ Qge,     const float4* __restrict__ Qgi,
    const float4* __restrict__ v_cut,   const float4* __restrict__ v_reset,
    const float4* __restrict__ t_refrac,
    const float* __restrict__ dt_ptr,
    float* __restrict__ out, int n4) {
    int i = blockIdx.x * blockDim.x + threadIdx.x;
    if (i >= n4) { cudaGridDependencySynchronize(); return; }
    int n = n4 * 4;

    // ---- pre-dependency loads (independent of edge kernel output) ----
    float dt = __ldg(dt_ptr);
    float4 v4  = voltage[i];
    float4 w4  = adapt[i];
    float4 ge4 = ge_in[i];
    float4 gi4 = gi_in[i];
    float4 Qe4 = Qge[i];
    float4 Qi4 = Qgi[i];
    float4 gl4 = g_L[i];
    float4 dT4 = delta_T[i];
    float4 vt4 = v_thresh[i];
    float4 vr4 = v_rest[i];
    float4 C4  = Cm[i];
    float4 a4  = aa[i];
    float4 b4  = bb[i];
    float4 tw4 = tau_w[i];
    float4 tge4 = tau_ge[i];
    float4 tgi4 = tau_gi[i];
    float4 Ege4 = E_ge[i];
    float4 Egi4 = E_gi[i];
    float4 Ib4  = I_bias[i];
    float4 ssc4 = stim_scale[i];
    float4 st4  = stim[i];
    float4 vc4  = v_cut[i];
    float4 vrs4 = v_reset[i];
    float4 tr4  = t_refrac[i];
    float4 rf4  = refr_in[i];

    // ---- wait for edge atomics, then consume + re-zero counts ----
    cudaGridDependencySynchronize();
    uint4 c4 = *reinterpret_cast<const uint4*>(g_cnt + i * 4);
    *reinterpret_cast<uint4*>(g_cnt + i * 4) = make_uint4(0u, 0u, 0u, 0u);
    unsigned int cl[4] = {c4.x, c4.y, c4.z, c4.w};

    float4 vo, wo, geo, gio, ro, so;
    int lane = 0;

#define LANE(F)                                                                 \
    {                                                                           \
        unsigned int cnt = cl[lane++];                                          \
        float v = v4.F, w = w4.F;                                               \
        float ge = ge4.F + Qe4.F * (float)(cnt & 0xffffu);                      \
        float gi = gi4.F + Qi4.F * (float)(cnt >> 16);                          \
        float gl = gl4.F, dT = dT4.F, vr = vr4.F;                               \
        float I = Ib4.F + ssc4.F * st4.F + ge * (Ege4.F - v) + gi * (Egi4.F - v); \
        float exp_term = gl * dT * expf(fminf((v - vt4.F) / dT, 20.0f));        \
        float dv = (-gl * (v - vr) + exp_term - w + I) / C4.F;                  \
        float dw = (-w + a4.F * (v - vr)) / tw4.F;                              \
        float refr = rf4.F;                                                     \
        float vn = (refr <= 0.0f) ? (v + dv * dt) : v;                          \
        float wn = w + dw * dt;                                                 \
        geo.F = ge - (ge / tge4.F) * dt;                                        \
        gio.F = gi - (gi / tgi4.F) * dt;                                        \
        bool spk = vn > vc4.F;                                                  \
        vo.F = spk ? vrs4.F : vn;                                               \
        wo.F = spk ? (wn + b4.F) : wn;                                          \
        ro.F = (spk ? tr4.F : refr) - dt;                                       \
        so.F = spk ? 1.0f : 0.0f;                                               \
    }
    LANE(x) LANE(y) LANE(z) LANE(w)
#undef LANE

    *reinterpret_cast<float4*>(out + 0 * n + i * 4) = vo;
    *reinterpret_cast<float4*>(out + 1 * n + i * 4) = wo;
    *reinterpret_cast<float4*>(out + 2 * n + i * 4) = geo;
    *reinterpret_cast<float4*>(out + 3 * n + i * 4) = gio;
    *reinterpret_cast<float4*>(out + 4 * n + i * 4) = ro;
    *reinterpret_cast<float4*>(out + 5 * n + i * 4) = so;
}

extern "C" void kernel_launch(void* const* d_in, const int* in_sizes, int n_in,
                              void* d_out, int out_size) {
    const float* voltage    = (const float*)d_in[0];
    const float* adapt      = (const float*)d_in[1];
    const float* ge         = (const float*)d_in[2];
    const float* gi         = (const float*)d_in[3];
    const float* stim       = (const float*)d_in[4];
    const float* refr       = (const float*)d_in[5];
    const float* g_L        = (const float*)d_in[6];
    const float* delta_T    = (const float*)d_in[7];
    const float* v_thresh   = (const float*)d_in[8];
    const float* v_rest     = (const float*)d_in[9];
    const float* C          = (const float*)d_in[10];
    const float* a          = (const float*)d_in[11];
    const float* b          = (const float*)d_in[12];
    const float* tau_w      = (const float*)d_in[13];
    const float* tau_ge     = (const float*)d_in[14];
    const float* tau_gi     = (const float*)d_in[15];
    const float* E_ge       = (const float*)d_in[16];
    const float* E_gi       = (const float*)d_in[17];
    const float* I_bias     = (const float*)d_in[18];
    const float* stim_scale = (const float*)d_in[19];
    const float* Q_ge       = (const float*)d_in[20];
    const float* Q_gi       = (const float*)d_in[21];
    const float* v_cut      = (const float*)d_in[22];
    const float* v_reset    = (const float*)d_in[23];
    const float* t_refrac   = (const float*)d_in[24];
    const float* spiked     = (const float*)d_in[25];
    const float* is_exc     = (const float*)d_in[26];
    const int*   edge_index = (const int*)d_in[27];
    const float* dt         = (const float*)d_in[28];

    int n = in_sizes[0];
    int n4 = n / 4;
    int E = in_sizes[27] / 2;
    const int* src = edge_index;
    const int* dst = edge_index + E;

    build_mask_kernel<<<(n + 255) / 256, 256>>>(spiked, is_exc, n);

    // PDL attribute: secondary may launch before primary completes; ordering
    // is enforced by cudaGridDependencySynchronize() inside the kernels.
    cudaLaunchAttribute pdl[1];
    pdl[0].id = cudaLaunchAttributeProgrammaticStreamSerialization;
    pdl[0].val.programmaticStreamSerializationAllowed = 1;

    {
        cudaLaunchConfig_t cfg = {};
        int edge_blocks = (E + EDGE_PER_BLOCK - 1) / EDGE_PER_BLOCK;
        cfg.gridDim  = dim3(edge_blocks, 1, 1);
        cfg.blockDim = dim3(EDGE_BLOCK, 1, 1);
        cfg.attrs = pdl;
        cfg.numAttrs = 1;
        cudaLaunchKernelEx(&cfg, edge_kernel, src, dst, E);
    }

    {
        cudaLaunchConfig_t cfg = {};
        cfg.gridDim  = dim3((n4 + 63) / 64, 1, 1);
        cfg.blockDim = dim3(64, 1, 1);
        cfg.attrs = pdl;
        cfg.numAttrs = 1;
        cudaLaunchKernelEx(&cfg, neuron_kernel,
            (const float4*)voltage, (const float4*)adapt,
            (const float4*)ge, (const float4*)gi,
            (const float4*)stim, (const float4*)refr,
            (const float4*)g_L, (const float4*)delta_T,
            (const float4*)v_thresh, (const float4*)v_rest,
            (const float4*)C, (const float4*)a, (const float4*)b,
            (const float4*)tau_w, (const float4*)tau_ge, (const float4*)tau_gi,
            (const float4*)E_ge, (const float4*)E_gi,
            (const float4*)I_bias, (const float4*)stim_scale,
            (const float4*)Q_ge, (const float4*)Q_gi,
            (const float4*)v_cut, (const float4*)v_reset, (const float4*)t_refrac,
            dt, (float*)d_out, n4);
    }
}

// round 9
// speedup vs baseline: 2.0955x; 1.0108x over previous
#include <cuda_runtime.h>
#include <cuda_bf16.h>

// Problem constants (fixed by dataset): N = 131072 neurons, E = N*64 edges.
#define MAX_N 131072
#define NWORDS (MAX_N / 32)     // 4096 words = 16 KB per bitmask

// Scratch: zero-initialized at load; neuron kernel consumes AND re-zeros so
// every graph replay starts clean (deterministic).
// Packed event counts: low 16 bits = excitatory arrivals, high 16 = inhibitory.
__device__ unsigned int g_cnt[MAX_N];
// Bit-planar spike tables: 1 bit/neuron.
__device__ unsigned int g_act[NWORDS];   // neuron spiked last step
__device__ unsigned int g_exc[NWORDS];   // spiked AND excitatory

// ---------------------------------------------------------------------------
// Kernel 1: build bitmasks. 1 neuron/thread, warp ballots, lane 0 writes.
// Bool inputs arrive as float32 (0.0 / 1.0).
// ---------------------------------------------------------------------------
__global__ void build_mask_kernel(const float* __restrict__ spiked,
                                  const float* __restrict__ is_exc,
                                  int n) {
    int i = blockIdx.x * blockDim.x + threadIdx.x;
    if (i >= n) return;
    bool s = spiked[i] != 0.0f;
    bool x = is_exc[i] != 0.0f;
    unsigned int act = __ballot_sync(0xffffffffu, s);
    unsigned int exc = __ballot_sync(0xffffffffu, s && x);
    if ((i & 31) == 0) {
        g_act[i >> 5] = act;
        g_exc[i >> 5] = exc;
    }
}

// ---------------------------------------------------------------------------
// Kernel 2: event-driven synaptic scatter (PDL secondary of build_mask).
// 32768 edges/block in 2 rounds of 4 int4 groups/thread -> exactly 256 blocks
// = ONE residency wave at 2 CTAs/SM (no wave tail). Round-0 src loads are
// front-batched BEFORE cudaGridDependencySynchronize: with all blocks resident,
// half the src stream (16.7 MB) overlaps the build kernel. 16 KB act + 16 KB
// exc bitmasks staged in smem; dst int4 loaded only for active groups; one
// packed-int atomic per active edge (no value gather).
// ---------------------------------------------------------------------------
#define EDGE_BLOCK  1024
#define EDGE_GPT    4                               // int4 groups per round
#define EDGE_ROUNDS 2
#define EDGE_PER_BLOCK (EDGE_BLOCK * EDGE_GPT * 4 * EDGE_ROUNDS)  // 32768

__global__ void __launch_bounds__(EDGE_BLOCK, 2)
edge_kernel(const int* __restrict__ src,
            const int* __restrict__ dst,
            int E) {
    __shared__ unsigned int s_act[NWORDS];   // 16 KB
    __shared__ unsigned int s_exc[NWORDS];   // 16 KB

    const int tid = threadIdx.x;
    long base = (long)blockIdx.x * EDGE_PER_BLOCK;
    bool full = (base + EDGE_PER_BLOCK) <= (long)E;

    const int4* src4 = reinterpret_cast<const int4*>(src + base);
    const int4* dst4 = reinterpret_cast<const int4*>(dst + base);

    // ---- pre-dependency: front-batch round-0 src (independent of build) ----
    int4 sb[EDGE_GPT];
    if (full) {
#pragma unroll
        for (int k = 0; k < EDGE_GPT; k++)
            sb[k] = src4[tid + k * EDGE_BLOCK];
    }

    // ---- wait for build_mask results, then stage tables ----
    cudaGridDependencySynchronize();
    {
        const uint4* ga = reinterpret_cast<const uint4*>(g_act);
        const uint4* gx = reinterpret_cast<const uint4*>(g_exc);
        reinterpret_cast<uint4*>(s_act)[tid] = ga[tid];
        reinterpret_cast<uint4*>(s_exc)[tid] = gx[tid];
    }
    __syncthreads();

    if (full) {
#pragma unroll
        for (int r = 0; r < EDGE_ROUNDS; r++) {
            if (r > 0) {
#pragma unroll
                for (int k = 0; k < EDGE_GPT; k++)
                    sb[k] = src4[tid + (r * EDGE_GPT + k) * EDGE_BLOCK];
            }
#pragma unroll
            for (int k = 0; k < EDGE_GPT; k++) {
                int ss[4] = {sb[k].x, sb[k].y, sb[k].z, sb[k].w};
                unsigned int aa[4];
                unsigned int any = 0;
#pragma unroll
                for (int j = 0; j < 4; j++) {
                    aa[j] = (s_act[ss[j] >> 5] >> (ss[j] & 31)) & 1u;
                    any |= aa[j];
                }
                if (any) {
                    int4 d4 = dst4[tid + (r * EDGE_GPT + k) * EDGE_BLOCK];
                    int dd[4] = {d4.x, d4.y, d4.z, d4.w};
#pragma unroll
                    for (int j = 0; j < 4; j++) {
                        if (aa[j]) {
                            int idx = ss[j];
                            bool e = (s_exc[idx >> 5] >> (idx & 31)) & 1u;
                            atomicAdd(&g_cnt[dd[j]], e ? 1u : 65536u);
                        }
                    }
                }
            }
        }
    } else {
        for (long e = base + tid; e < E; e += EDGE_BLOCK) {
            int idx = src[e];
            if ((s_act[idx >> 5] >> (idx & 31)) & 1u) {
                bool ex = (s_exc[idx >> 5] >> (idx & 31)) & 1u;
                atomicAdd(&g_cnt[dst[e]], ex ? 1u : 65536u);
            }
        }
    }
}

// ---------------------------------------------------------------------------
// Kernel 3: AdEx neuron update, float4-vectorized (PDL secondary of edge).
// All parameter streams are loaded BEFORE the dependency sync; only the
// packed-count consumption waits for the edge atomics.
// ge += Q_ge * exc_count ; gi += Q_gi * inh_count  (Q read coalesced here).
// ---------------------------------------------------------------------------
__global__ void neuron_kernel(
    const float4* __restrict__ voltage, const float4* __restrict__ adapt,
    const float4* __restrict__ ge_in,   const float4* __restrict__ gi_in,
    const float4* __restrict__ stim,    const float4* __restrict__ refr_in,
    const float4* __restrict__ g_L,     const float4* __restrict__ delta_T,
    const float4* __restrict__ v_thresh,const float4* __restrict__ v_rest,
    const float4* __restrict__ Cm,      const float4* __restrict__ aa,
    const float4* __restrict__ bb,      const float4* __restrict__ tau_w,
    const float4* __restrict__ tau_ge,  const float4* __restrict__ tau_gi,
    const float4* __restrict__ E_ge,    const float4* __restrict__ E_gi,
    const float4* __restrict__ I_bias,  const float4* __restrict__ stim_scale,
    const float4* __restrict__ Qge,     const float4* __restrict__ Qgi,
    const float4* __restrict__ v_cut,   const float4* __restrict__ v_reset,
    const float4* __restrict__ t_refrac,
    const float* __restrict__ dt_ptr,
    float* __restrict__ out, int n4) {
    int i = blockIdx.x * blockDim.x + threadIdx.x;
    if (i >= n4) { cudaGridDependencySynchronize(); return; }
    int n = n4 * 4;

    // ---- pre-dependency loads (independent of edge kernel output) ----
    float dt = __ldg(dt_ptr);
    float4 v4  = voltage[i];
    float4 w4  = adapt[i];
    float4 ge4 = ge_in[i];
    float4 gi4 = gi_in[i];
    float4 Qe4 = Qge[i];
    float4 Qi4 = Qgi[i];
    float4 gl4 = g_L[i];
    float4 dT4 = delta_T[i];
    float4 vt4 = v_thresh[i];
    float4 vr4 = v_rest[i];
    float4 C4  = Cm[i];
    float4 a4  = aa[i];
    float4 b4  = bb[i];
    float4 tw4 = tau_w[i];
    float4 tge4 = tau_ge[i];
    float4 tgi4 = tau_gi[i];
    float4 Ege4 = E_ge[i];
    float4 Egi4 = E_gi[i];
    float4 Ib4  = I_bias[i];
    float4 ssc4 = stim_scale[i];
    float4 st4  = stim[i];
    float4 vc4  = v_cut[i];
    float4 vrs4 = v_reset[i];
    float4 tr4  = t_refrac[i];
    float4 rf4  = refr_in[i];

    // ---- wait for edge atomics, then consume + re-zero counts ----
    cudaGridDependencySynchronize();
    uint4 c4 = *reinterpret_cast<const uint4*>(g_cnt + i * 4);
    *reinterpret_cast<uint4*>(g_cnt + i * 4) = make_uint4(0u, 0u, 0u, 0u);
    unsigned int cl[4] = {c4.x, c4.y, c4.z, c4.w};

    float4 vo, wo, geo, gio, ro, so;
    int lane = 0;

#define LANE(F)                                                                 \
    {                                                                           \
        unsigned int cnt = cl[lane++];                                          \
        float v = v4.F, w = w4.F;                                               \
        float ge = ge4.F + Qe4.F * (float)(cnt & 0xffffu);                      \
        float gi = gi4.F + Qi4.F * (float)(cnt >> 16);                          \
        float gl = gl4.F, dT = dT4.F, vr = vr4.F;                               \
        float I = Ib4.F + ssc4.F * st4.F + ge * (Ege4.F - v) + gi * (Egi4.F - v); \
        float exp_term = gl * dT * expf(fminf((v - vt4.F) / dT, 20.0f));        \
        float dv = (-gl * (v - vr) + exp_term - w + I) / C4.F;                  \
        float dw = (-w + a4.F * (v - vr)) / tw4.F;                              \
        float refr = rf4.F;                                                     \
        float vn = (refr <= 0.0f) ? (v + dv * dt) : v;                          \
        float wn = w + dw * dt;                                                 \
        geo.F = ge - (ge / tge4.F) * dt;                                        \
        gio.F = gi - (gi / tgi4.F) * dt;                                        \
        bool spk = vn > vc4.F;                                                  \
        vo.F = spk ? vrs4.F : vn;                                               \
        wo.F = spk ? (wn + b4.F) : wn;                                          \
        ro.F = (spk ? tr4.F : refr) - dt;                                       \
        so.F = spk ? 1.0f : 0.0f;                                               \
    }
    LANE(x) LANE(y) LANE(z) LANE(w)
#undef LANE

    *reinterpret_cast<float4*>(out + 0 * n + i * 4) = vo;
    *reinterpret_cast<float4*>(out + 1 * n + i * 4) = wo;
    *reinterpret_cast<float4*>(out + 2 * n + i * 4) = geo;
    *reinterpret_cast<float4*>(out + 3 * n + i * 4) = gio;
    *reinterpret_cast<float4*>(out + 4 * n + i * 4) = ro;
    *reinterpret_cast<float4*>(out + 5 * n + i * 4) = so;
}

extern "C" void kernel_launch(void* const* d_in, const int* in_sizes, int n_in,
                              void* d_out, int out_size) {
    const float* voltage    = (const float*)d_in[0];
    const float* adapt      = (const float*)d_in[1];
    const float* ge         = (const float*)d_in[2];
    const float* gi         = (const float*)d_in[3];
    const float* stim       = (const float*)d_in[4];
    const float* refr       = (const float*)d_in[5];
    const float* g_L        = (const float*)d_in[6];
    const float* delta_T    = (const float*)d_in[7];
    const float* v_thresh   = (const float*)d_in[8];
    const float* v_rest     = (const float*)d_in[9];
    const float* C          = (const float*)d_in[10];
    const float* a          = (const float*)d_in[11];
    const float* b          = (const float*)d_in[12];
    const float* tau_w      = (const float*)d_in[13];
    const float* tau_ge     = (const float*)d_in[14];
    const float* tau_gi     = (const float*)d_in[15];
    const float* E_ge       = (const float*)d_in[16];
    const float* E_gi       = (const float*)d_in[17];
    const float* I_bias     = (const float*)d_in[18];
    const float* stim_scale = (const float*)d_in[19];
    const float* Q_ge       = (const float*)d_in[20];
    const float* Q_gi       = (const float*)d_in[21];
    const float* v_cut      = (const float*)d_in[22];
    const float* v_reset    = (const float*)d_in[23];
    const float* t_refrac   = (const float*)d_in[24];
    const float* spiked     = (const float*)d_in[25];
    const float* is_exc     = (const float*)d_in[26];
    const int*   edge_index = (const int*)d_in[27];
    const float* dt         = (const float*)d_in[28];

    int n = in_sizes[0];
    int n4 = n / 4;
    int E = in_sizes[27] / 2;
    const int* src = edge_index;
    const int* dst = edge_index + E;

    build_mask_kernel<<<(n + 255) / 256, 256>>>(spiked, is_exc, n);

    // PDL attribute: secondary may launch before primary completes; ordering
    // is enforced by cudaGridDependencySynchronize() inside the kernels.
    cudaLaunchAttribute pdl[1];
    pdl[0].id = cudaLaunchAttributeProgrammaticStreamSerialization;
    pdl[0].val.programmaticStreamSerializationAllowed = 1;

    {
        cudaLaunchConfig_t cfg = {};
        int edge_blocks = (E + EDGE_PER_BLOCK - 1) / EDGE_PER_BLOCK;
        cfg.gridDim  = dim3(edge_blocks, 1, 1);
        cfg.blockDim = dim3(EDGE_BLOCK, 1, 1);
        cfg.attrs = pdl;
        cfg.numAttrs = 1;
        cudaLaunchKernelEx(&cfg, edge_kernel, src, dst, E);
    }

    {
        cudaLaunchConfig_t cfg = {};
        cfg.gridDim  = dim3((n4 + 63) / 64, 1, 1);
        cfg.blockDim = dim3(64, 1, 1);
        cfg.attrs = pdl;
        cfg.numAttrs = 1;
        cudaLaunchKernelEx(&cfg, neuron_kernel,
            (const float4*)voltage, (const float4*)adapt,
            (const float4*)ge, (const float4*)gi,
            (const float4*)stim, (const float4*)refr,
            (const float4*)g_L, (const float4*)delta_T,
            (const float4*)v_thresh, (const float4*)v_rest,
            (const float4*)C, (const float4*)a, (const float4*)b,
            (const float4*)tau_w, (const float4*)tau_ge, (const float4*)tau_gi,
            (const float4*)E_ge, (const float4*)E_gi,
            (const float4*)I_bias, (const float4*)stim_scale,
            (const float4*)Q_ge, (const float4*)Q_gi,
            (const float4*)v_cut, (const float4*)v_reset, (const float4*)t_refrac,
            dt, (float*)d_out, n4);
    }
}